// round 1
// baseline (speedup 1.0000x reference)
#include <cuda_runtime.h>
#include <stdint.h>

#define LOG2_HASHMAP_SIZE 19
#define HASHTABLE_SIZE (1u << LOG2_HASHMAP_SIZE)
#define HASH_MASK (HASHTABLE_SIZE - 1u)
#define RES 128.0f

__device__ __forceinline__ uint32_t hash3(uint32_t ix, uint32_t iy, uint32_t iz) {
    return (ix ^ (iy * 2654435761u) ^ (iz * 805459861u)) & HASH_MASK;
}

__global__ void __launch_bounds__(256) ngp_interp_kernel(
    const float* __restrict__ x,
    const float2* __restrict__ ht,
    float2* __restrict__ out,
    int n)
{
    int i = blockIdx.x * blockDim.x + threadIdx.x;
    if (i >= n) return;

    float px = x[3 * i + 0];
    float py = x[3 * i + 1];
    float pz = x[3 * i + 2];

    float sx = px * RES;
    float sy = py * RES;
    float sz = pz * RES;

    float fxf = floorf(sx), fyf = floorf(sy), fzf = floorf(sz);
    int fx = (int)fxf, fy = (int)fyf, fz = (int)fzf;
    int cx = (int)ceilf(sx), cy = (int)ceilf(sy), cz = (int)ceilf(sz);

    float dx = sx - fxf;
    float dy = sy - fyf;
    float dz = sz - fzf;

    uint32_t h000 = hash3((uint32_t)fx, (uint32_t)fy, (uint32_t)fz);
    uint32_t h100 = hash3((uint32_t)cx, (uint32_t)fy, (uint32_t)fz);
    uint32_t h010 = hash3((uint32_t)fx, (uint32_t)cy, (uint32_t)fz);
    uint32_t h001 = hash3((uint32_t)fx, (uint32_t)fy, (uint32_t)cz);
    uint32_t h110 = hash3((uint32_t)cx, (uint32_t)cy, (uint32_t)fz);
    uint32_t h101 = hash3((uint32_t)cx, (uint32_t)fy, (uint32_t)cz);
    uint32_t h011 = hash3((uint32_t)fx, (uint32_t)cy, (uint32_t)cz);
    uint32_t h111 = hash3((uint32_t)cx, (uint32_t)cy, (uint32_t)cz);

    // 8 independent gathers — MLP=8, latency hidden at occupancy.
    float2 v000 = __ldg(&ht[h000]);
    float2 v100 = __ldg(&ht[h100]);
    float2 v010 = __ldg(&ht[h010]);
    float2 v001 = __ldg(&ht[h001]);
    float2 v110 = __ldg(&ht[h110]);
    float2 v101 = __ldg(&ht[h101]);
    float2 v011 = __ldg(&ht[h011]);
    float2 v111 = __ldg(&ht[h111]);

    float omx = 1.0f - dx;
    float omy = 1.0f - dy;
    float omz = 1.0f - dz;

    // Match reference lerp order exactly.
    float c00a = v000.x * omx + v100.x * dx;
    float c00b = v000.y * omx + v100.y * dx;
    float c01a = v001.x * omx + v101.x * dx;
    float c01b = v001.y * omx + v101.y * dx;
    float c10a = v010.x * omx + v110.x * dx;
    float c10b = v010.y * omx + v110.y * dx;
    float c11a = v011.x * omx + v111.x * dx;
    float c11b = v011.y * omx + v111.y * dx;

    float c0a = c00a * omy + c10a * dy;
    float c0b = c00b * omy + c10b * dy;
    float c1a = c01a * omy + c11a * dy;
    float c1b = c01b * omy + c11b * dy;

    float oa = c0a * omz + c1a * dz;
    float ob = c0b * omz + c1b * dz;

    out[i] = make_float2(oa, ob);
}

extern "C" void kernel_launch(void* const* d_in, const int* in_sizes, int n_in,
                              void* d_out, int out_size) {
    const float* x = (const float*)d_in[0];
    const float2* ht = (const float2*)d_in[1];
    float2* out = (float2*)d_out;
    int n = in_sizes[0] / 3;

    int threads = 256;
    int blocks = (n + threads - 1) / threads;
    ngp_interp_kernel<<<blocks, threads>>>(x, ht, out, n);
}

// round 2
// speedup vs baseline: 1.0726x; 1.0726x over previous
#include <cuda_runtime.h>
#include <stdint.h>

#define LOG2_HASHMAP_SIZE 19
#define HASHTABLE_SIZE (1u << LOG2_HASHMAP_SIZE)
#define HASH_MASK (HASHTABLE_SIZE - 1u)
#define RES 128.0f
#define P1 2654435761u
#define P2 805459861u

__device__ __forceinline__ void pair_load_merged(
    const float4* __restrict__ ht4, uint32_t hA,
    float2& vA, float2& vB)
{
    // hB == hA ^ 1: both entries live in one aligned 16B float4.
    float4 q = __ldg(&ht4[hA >> 1]);
    bool odd = (hA & 1u) != 0u;
    vA = odd ? make_float2(q.z, q.w) : make_float2(q.x, q.y);
    vB = odd ? make_float2(q.x, q.y) : make_float2(q.z, q.w);
}

__global__ void __launch_bounds__(256) ngp_interp_kernel(
    const float* __restrict__ x,
    const float2* __restrict__ ht,
    float2* __restrict__ out,
    int n)
{
    int i = blockIdx.x * blockDim.x + threadIdx.x;
    if (i >= n) return;

    float px = x[3 * i + 0];
    float py = x[3 * i + 1];
    float pz = x[3 * i + 2];

    float sx = px * RES;
    float sy = py * RES;
    float sz = pz * RES;

    float fxf = floorf(sx), fyf = floorf(sy), fzf = floorf(sz);
    uint32_t ufx = (uint32_t)(int)fxf;
    uint32_t ufy = (uint32_t)(int)fyf;
    uint32_t ufz = (uint32_t)(int)fzf;
    uint32_t ucx = (uint32_t)(int)ceilf(sx);
    uint32_t ucy = (uint32_t)(int)ceilf(sy);
    uint32_t ucz = (uint32_t)(int)ceilf(sz);

    float dx = sx - fxf;
    float dy = sy - fyf;
    float dz = sz - fzf;

    // y/z mix terms (shared across the 4 x-pairs)
    uint32_t yfP = ufy * P1, ycP = ucy * P1;
    uint32_t zfP = ufz * P2, zcP = ucz * P2;
    uint32_t mff = yfP ^ zfP;
    uint32_t mcf = ycP ^ zfP;
    uint32_t mfc = yfP ^ zcP;
    uint32_t mcc = ycP ^ zcP;

    uint32_t h000 = (ufx ^ mff) & HASH_MASK;
    uint32_t h010 = (ufx ^ mcf) & HASH_MASK;
    uint32_t h001 = (ufx ^ mfc) & HASH_MASK;
    uint32_t h011 = (ufx ^ mcc) & HASH_MASK;

    uint32_t dxor = ufx ^ ucx;  // hash is XOR-linear in ix: h1 = h0 ^ dxor

    float2 v000, v100, v010, v110, v001, v101, v011, v111;

    if (dxor == 1u) {
        // All 4 x-pairs are adjacent aligned entries: 4x LDG.128 instead of 8x LDG.64
        const float4* ht4 = (const float4*)ht;
        pair_load_merged(ht4, h000, v000, v100);
        pair_load_merged(ht4, h010, v010, v110);
        pair_load_merged(ht4, h001, v001, v101);
        pair_load_merged(ht4, h011, v011, v111);
    } else {
        uint32_t h100 = (ucx ^ mff) & HASH_MASK;
        uint32_t h110 = (ucx ^ mcf) & HASH_MASK;
        uint32_t h101 = (ucx ^ mfc) & HASH_MASK;
        uint32_t h111 = (ucx ^ mcc) & HASH_MASK;
        v000 = __ldg(&ht[h000]);
        v100 = __ldg(&ht[h100]);
        v010 = __ldg(&ht[h010]);
        v110 = __ldg(&ht[h110]);
        v001 = __ldg(&ht[h001]);
        v101 = __ldg(&ht[h101]);
        v011 = __ldg(&ht[h011]);
        v111 = __ldg(&ht[h111]);
    }

    float omx = 1.0f - dx;
    float omy = 1.0f - dy;
    float omz = 1.0f - dz;

    // Match reference lerp order exactly.
    float c00a = v000.x * omx + v100.x * dx;
    float c00b = v000.y * omx + v100.y * dx;
    float c01a = v001.x * omx + v101.x * dx;
    float c01b = v001.y * omx + v101.y * dx;
    float c10a = v010.x * omx + v110.x * dx;
    float c10b = v010.y * omx + v110.y * dx;
    float c11a = v011.x * omx + v111.x * dx;
    float c11b = v011.y * omx + v111.y * dx;

    float c0a = c00a * omy + c10a * dy;
    float c0b = c00b * omy + c10b * dy;
    float c1a = c01a * omy + c11a * dy;
    float c1b = c01b * omy + c11b * dy;

    float oa = c0a * omz + c1a * dz;
    float ob = c0b * omz + c1b * dz;

    out[i] = make_float2(oa, ob);
}

extern "C" void kernel_launch(void* const* d_in, const int* in_sizes, int n_in,
                              void* d_out, int out_size) {
    const float* x = (const float*)d_in[0];
    const float2* ht = (const float2*)d_in[1];
    float2* out = (float2*)d_out;
    int n = in_sizes[0] / 3;

    int threads = 256;
    int blocks = (n + threads - 1) / threads;
    ngp_interp_kernel<<<blocks, threads>>>(x, ht, out, n);
}